// round 16
// baseline (speedup 1.0000x reference)
#include <cuda_runtime.h>
#include <cuda_bf16.h>
#include <cuda_fp16.h>
#include <cstdint>

#define BATCH 2
#define SEQ   2048
#define DIMSZ 1024
#define HEADS 16
#define DHEAD 64
#define INNER 1024
#define QKV3  3072
#define ROWS  (BATCH * SEQ)   // 4096

// ---------------- scratch (static device globals; no allocation) -------------
__device__ __half g_qkvh[ROWS * QKV3];    // 25 MB fp16 (Q prescaled by 0.125)
__device__ __half g_xnh[ROWS * DIMSZ];    // LN out fp16
__device__ __half g_wqh[DIMSZ * QKV3];    // Wqkv fp16, natural [K][N]
__device__ __half g_woh[INNER * DIMSZ];   // Wout fp16, natural [K][N]
__device__ __half g_aoh[ROWS * INNER];    // attention out fp16

// ---------------- helpers ----------------------------------------------------
__device__ __forceinline__ uint32_t smem_u32(const void* p) {
    uint32_t a;
    asm("{ .reg .u64 t; cvta.to.shared.u64 t, %1; cvt.u32.u64 %0, t; }"
        : "=r"(a) : "l"(p));
    return a;
}
__device__ __forceinline__ void cp16(uint32_t dst, const void* src) {
    asm volatile("cp.async.cg.shared.global [%0], [%1], 16;"
                 :: "r"(dst), "l"(src) : "memory");
}
__device__ __forceinline__ void ldm4(uint32_t* r, uint32_t addr) {
    asm volatile("ldmatrix.sync.aligned.m8n8.x4.shared.b16 {%0,%1,%2,%3}, [%4];"
        : "=r"(r[0]), "=r"(r[1]), "=r"(r[2]), "=r"(r[3]) : "r"(addr));
}
__device__ __forceinline__ void ldm4t(uint32_t* r, uint32_t addr) {
    asm volatile("ldmatrix.sync.aligned.m8n8.x4.trans.shared.b16 {%0,%1,%2,%3}, [%4];"
        : "=r"(r[0]), "=r"(r[1]), "=r"(r[2]), "=r"(r[3]) : "r"(addr));
}
__device__ __forceinline__ void mma_f16(float* d, const uint32_t* a,
                                        uint32_t b0, uint32_t b1) {
    asm volatile("mma.sync.aligned.m16n8k16.row.col.f32.f16.f16.f32 "
        "{%0,%1,%2,%3}, {%4,%5,%6,%7}, {%8,%9}, {%0,%1,%2,%3};"
        : "+f"(d[0]), "+f"(d[1]), "+f"(d[2]), "+f"(d[3])
        : "r"(a[0]), "r"(a[1]), "r"(a[2]), "r"(a[3]), "r"(b0), "r"(b1));
}
// fp16-accumulator MMA: d = {c0c1(row r), c2c3(row r+8)} packed half2
__device__ __forceinline__ void mma_f16h(uint32_t* d, const uint32_t* a,
                                         uint32_t b0, uint32_t b1) {
    asm volatile("mma.sync.aligned.m16n8k16.row.col.f16.f16.f16.f16 "
        "{%0,%1}, {%2,%3,%4,%5}, {%6,%7}, {%0,%1};"
        : "+r"(d[0]), "+r"(d[1])
        : "r"(a[0]), "r"(a[1]), "r"(a[2]), "r"(a[3]), "r"(b0), "r"(b1));
}
__device__ __forceinline__ uint32_t h2u(float a, float b) {
    __half2 h = __floats2half2_rn(a, b);
    return *reinterpret_cast<uint32_t*>(&h);
}
__device__ __forceinline__ float2 u2f2(uint32_t u) {
    return __half22float2(*reinterpret_cast<__half2*>(&u));
}
__device__ __forceinline__ uint32_t ex2_h2(uint32_t packed) {
    uint32_t r;
    asm("ex2.approx.f16x2 %0, %1;" : "=r"(r) : "r"(packed));
    return r;
}
__device__ __forceinline__ uint32_t hadd2u(uint32_t a, uint32_t b) {
    uint32_t r;
    asm("add.f16x2 %0, %1, %2;" : "=r"(r) : "r"(a), "r"(b));
    return r;
}

// ------------- fused LayerNorm (blocks < ROWS) + weight convert --------------
#define CONV_N1 ((QKV3 * DIMSZ) / 4)      // 786432 float4
#define CONV_N2 ((DIMSZ * INNER) / 4)     // 262144 float4
#define CONV_BLOCKS ((CONV_N1 + CONV_N2) / 256)   // 4096

__global__ void __launch_bounds__(256) ln_conv_kernel(
    const float* __restrict__ x, const float* __restrict__ gamma,
    const float* __restrict__ beta, __half* __restrict__ o,
    const float* __restrict__ w1, const float* __restrict__ w2,
    __half* __restrict__ o1, __half* __restrict__ o2)
{
    int t = threadIdx.x;
    if (blockIdx.x >= ROWS) {
        int idx = (blockIdx.x - ROWS) * 256 + t;
        if (idx < CONV_N1) {
            float4 v = reinterpret_cast<const float4*>(w1)[idx];
            uint2 pk = {h2u(v.x, v.y), h2u(v.z, v.w)};
            reinterpret_cast<uint2*>(o1)[idx] = pk;
        } else {
            float4 v = reinterpret_cast<const float4*>(w2)[idx - CONV_N1];
            uint2 pk = {h2u(v.x, v.y), h2u(v.z, v.w)};
            reinterpret_cast<uint2*>(o2)[idx - CONV_N1] = pk;
        }
        return;
    }
    int row = blockIdx.x;
    const float4* xr = reinterpret_cast<const float4*>(x + (size_t)row * DIMSZ);
    float4 v = xr[t];
    float s  = v.x + v.y + v.z + v.w;
    float ss = v.x*v.x + v.y*v.y + v.z*v.z + v.w*v.w;
    #pragma unroll
    for (int off = 16; off; off >>= 1) {
        s  += __shfl_xor_sync(0xffffffffu, s,  off);
        ss += __shfl_xor_sync(0xffffffffu, ss, off);
    }
    __shared__ float sbuf[8], ssbuf[8];
    __shared__ float s_mu, s_rstd;
    int w = t >> 5, lane = t & 31;
    if (lane == 0) { sbuf[w] = s; ssbuf[w] = ss; }
    __syncthreads();
    if (t == 0) {
        float S = 0.f, SS = 0.f;
        #pragma unroll
        for (int i = 0; i < 8; i++) { S += sbuf[i]; SS += ssbuf[i]; }
        float mu = S * (1.0f / DIMSZ);
        float var = SS * (1.0f / DIMSZ) - mu * mu;
        s_mu = mu; s_rstd = rsqrtf(var + 1e-5f);
    }
    __syncthreads();
    float mu = s_mu, rstd = s_rstd;
    float4 g  = reinterpret_cast<const float4*>(gamma)[t];
    float4 bt = reinterpret_cast<const float4*>(beta)[t];
    float o0 = (v.x - mu) * rstd * g.x + bt.x;
    float o1v = (v.y - mu) * rstd * g.y + bt.y;
    float o2v = (v.z - mu) * rstd * g.z + bt.z;
    float o3 = (v.w - mu) * rstd * g.w + bt.w;
    uint2 pk = {h2u(o0, o1v), h2u(o2v, o3)};
    *reinterpret_cast<uint2*>(o + (size_t)row * DIMSZ + t * 4) = pk;
}

// ---------------- fp16 warp-mma GEMM, BK=64, natural-layout B ----------------
#define HS_AROW   144
#define HS_AARR   (128 * HS_AROW)      // 18432
#define HS_BARR   (64 * 256)           // 16384
#define HS_STAGE  (HS_AARR + HS_BARR)  // 34816
#define HS_NSTAGE 3
#define HS_SMEM   (HS_NSTAGE * HS_STAGE)   // 104448

template <bool HALF_OUT>
__global__ void __launch_bounds__(256, 2) hf_gemm_kernel(
    const __half* __restrict__ A, const __half* __restrict__ B,
    const float* __restrict__ bias, void* __restrict__ Cv, int Ntot)
{
    extern __shared__ char sm[];
    const int tid = threadIdx.x, lane = tid & 31, wid = tid >> 5;
    const int wm = wid >> 2, wn = wid & 3;
    const int c0 = blockIdx.x * 128, r0 = blockIdx.y * 128;
    const int lr = lane >> 2, lc = lane & 3;
    uint32_t sbase = smem_u32(sm);

    auto issue = [&](int c, int st) {
        int k0 = c * 64;
        uint32_t sb = sbase + st * HS_STAGE;
        #pragma unroll
        for (int i = 0; i < 8; i++) {
            int q = tid + i * 256;
            if (q < 1024) {
                int row = q >> 3, seg = q & 7;
                cp16(sb + row * HS_AROW + seg * 16,
                     A + (size_t)(r0 + row) * 1024 + k0 + seg * 8);
            } else {
                int rem = q - 1024;
                int row = rem >> 4, seg = rem & 15;
                uint32_t off = (uint32_t)(row * 256 + seg * 16);
                off ^= (uint32_t)(row & 7) << 4;
                cp16(sb + HS_AARR + off,
                     B + (size_t)(k0 + row) * Ntot + c0 + seg * 8);
            }
        }
        asm volatile("cp.async.commit_group;" ::: "memory");
    };

    float acc[4][4][4];
    #pragma unroll
    for (int a = 0; a < 4; a++)
        #pragma unroll
        for (int b = 0; b < 4; b++)
            #pragma unroll
            for (int cc = 0; cc < 4; cc++) acc[a][b][cc] = 0.f;

    issue(0, 0);
    issue(1, 1);

    const int mat  = lane >> 3;
    const int roff = (mat & 1) * 8 + (lane & 7);
    const int cofs = (mat >> 1) * 16;
    const uint32_t swzB = (uint32_t)(lane & 7) << 4;

    const int NCHUNK = 1024 / 64;   // 16
    int st = 0;
    for (int c = 0; c < NCHUNK; c++) {
        asm volatile("cp.async.wait_group 1;" ::: "memory");
        __syncthreads();

        int st2 = st + 2; if (st2 >= 3) st2 -= 3;
        if (c + 2 < NCHUNK) issue(c + 2, st2);
        else asm volatile("cp.async.commit_group;" ::: "memory");

        uint32_t base = sbase + st * HS_STAGE;

        #pragma unroll
        for (int ks = 0; ks < 4; ks++) {
            uint32_t ah[4][4], bh[2][4];
            #pragma unroll
            for (int nt2 = 0; nt2 < 2; nt2++) {
                uint32_t off = (uint32_t)((ks*16 + roff) * 256
                                          + wn*64 + nt2*32 + cofs) ^ swzB;
                ldm4t(bh[nt2], base + HS_AARR + off);
            }
            #pragma unroll
            for (int mt = 0; mt < 4; mt++)
                ldm4(ah[mt], base + (wm*64 + mt*16 + roff) * HS_AROW
                              + ks*32 + cofs);

            #pragma unroll
            for (int mt = 0; mt < 4; mt++)
                #pragma unroll
                for (int nt = 0; nt < 4; nt++) {
                    int n2 = nt >> 1, hf = nt & 1;
                    mma_f16(acc[mt][nt], ah[mt], bh[n2][2*hf], bh[n2][2*hf+1]);
                }
        }
        if (++st >= 3) st = 0;
    }

    #pragma unroll
    for (int mt = 0; mt < 4; mt++) {
        int rbase = r0 + wm*64 + mt*16 + lr;
        #pragma unroll
        for (int nt = 0; nt < 4; nt++) {
            int col = c0 + wn*32 + nt*8 + 2*lc;
            if (HALF_OUT) {
                __half* C = (__half*)Cv;
                float sc = (col < 1024) ? 0.125f : 1.0f;   // Q prescale
                *reinterpret_cast<uint32_t*>(C + (size_t)rbase * Ntot + col) =
                    h2u(acc[mt][nt][0] * sc, acc[mt][nt][1] * sc);
                *reinterpret_cast<uint32_t*>(C + (size_t)(rbase + 8) * Ntot + col) =
                    h2u(acc[mt][nt][2] * sc, acc[mt][nt][3] * sc);
            } else {
                float* C = (float*)Cv;
                float b0v = bias ? bias[col] : 0.f;
                float b1v = bias ? bias[col + 1] : 0.f;
                float2 v0 = {acc[mt][nt][0] + b0v, acc[mt][nt][1] + b1v};
                float2 v1 = {acc[mt][nt][2] + b0v, acc[mt][nt][3] + b1v};
                *reinterpret_cast<float2*>(C + (size_t)rbase * Ntot + col) = v0;
                *reinterpret_cast<float2*>(C + (size_t)(rbase + 8) * Ntot + col) = v1;
            }
        }
    }
}

// ---------------- flash attention: fp16 QK + f16x2 softmax + f16-acc PV ------
#define FA_QS    18432                    // Q: 128 * 144
#define FA_KB    9216                     // K stage: 64 * 144
#define FA_VB    8192                     // V stage: 64 * 128
#define FA_STAGE (FA_KB + FA_VB)          // 17408
#define FAH_SMEM (FA_QS + 2 * FA_STAGE)   // 53248

__global__ void __launch_bounds__(256, 2) fa_kernel(
    const __half* __restrict__ qkv, __half* __restrict__ outh)
{
    extern __shared__ char sm[];
    const int tid = threadIdx.x, lane = tid & 31, wid = tid >> 5;
    const int qt = blockIdx.x, hd = blockIdx.y, b = blockIdx.z;
    const int n0 = qt * 128;
    const int lr = lane >> 2, lc = lane & 3;
    uint32_t sbase = smem_u32(sm);

    const __half* qb = qkv + (size_t)b * SEQ * QKV3 + hd * DHEAD;
    const __half* kb = qb + 1024;
    const __half* vb = qb + 2048;

    #pragma unroll
    for (int i = 0; i < 4; i++) {
        int q = tid + i * 256;
        int row = q >> 3, ch = q & 7;
        cp16(sbase + row * 144 + ch * 16,
             qb + (size_t)(n0 + row) * QKV3 + ch * 8);
    }
    asm volatile("cp.async.commit_group;" ::: "memory");

    auto issueKV = [&](int kt, int st) {
        int s0 = kt * 64;
        uint32_t kbase = sbase + FA_QS + st * FA_STAGE;
        uint32_t vbase = kbase + FA_KB;
        #pragma unroll
        for (int i = 0; i < 4; i++) {
            int q = tid + i * 256;
            int arr = q >> 9, rem = q & 511;
            int row = rem >> 3, ch = rem & 7;
            if (arr == 0) {
                cp16(kbase + row * 144 + ch * 16,
                     kb + (size_t)(s0 + row) * QKV3 + ch * 8);
            } else {
                uint32_t off = (uint32_t)(row * 128 + ch * 16);
                off ^= ((off >> 7) & 7) << 4;
                cp16(vbase + off, vb + (size_t)(s0 + row) * QKV3 + ch * 8);
            }
        }
        asm volatile("cp.async.commit_group;" ::: "memory");
    };

    issueKV(0, 0);
    asm volatile("cp.async.wait_group 0;" ::: "memory");
    __syncthreads();

    const uint32_t* Qs = reinterpret_cast<const uint32_t*>(sm);
    uint32_t qa[4][4];
    {
        int m0 = wid * 16;
        #pragma unroll
        for (int u = 0; u < 4; u++) {
            qa[u][0] = Qs[(m0 + lr)     * 36 + u*8 + lc];
            qa[u][1] = Qs[(m0 + 8 + lr) * 36 + u*8 + lc];
            qa[u][2] = Qs[(m0 + lr)     * 36 + u*8 + lc + 4];
            qa[u][3] = Qs[(m0 + 8 + lr) * 36 + u*8 + lc + 4];
        }
    }

    const int mat  = lane >> 3;
    const int roff = (mat & 1) * 8 + (lane & 7);
    const int cofs = (mat >> 1) * 16;
    const float LOG2E = 1.44269504f;

    float m_i[2] = {-1e30f, -1e30f};
    float l_p[2] = {0.f, 0.f};
    float o[8][4];
    #pragma unroll
    for (int v = 0; v < 8; v++)
        #pragma unroll
        for (int j = 0; j < 4; j++) o[v][j] = 0.f;

    const int NT = SEQ / 64;   // 32
    for (int kt = 0; kt < NT; kt++) {
        if (kt > 0) {
            asm volatile("cp.async.wait_group 0;" ::: "memory");
            __syncthreads();
        }
        if (kt + 1 < NT) issueKV(kt + 1, (kt + 1) & 1);

        int st = kt & 1;
        uint32_t kbase = sbase + FA_QS + st * FA_STAGE;
        const uint32_t vsb = kbase + FA_KB;

        float s[8][4];
        #pragma unroll
        for (int v = 0; v < 8; v++)
            #pragma unroll
            for (int j = 0; j < 4; j++) s[v][j] = 0.f;
        #pragma unroll
        for (int u = 0; u < 4; u++) {
            uint32_t bh[4][4];
            #pragma unroll
            for (int g = 0; g < 4; g++)
                ldm4(bh[g], kbase + (g*16 + roff) * 144 + u*32 + cofs);
            #pragma unroll
            for (int v = 0; v < 8; v++) {
                int g = v >> 1, hf = v & 1;
                mma_f16(s[v], qa[u], bh[g][hf], bh[g][2+hf]);
            }
        }

        // online softmax; deferred l reduction, half2 sum tree
        uint32_t ph[8][2];
        float alpha[2];
        #pragma unroll
        for (int h = 0; h < 2; h++) {
            float mx = -1e30f;
            #pragma unroll
            for (int v = 0; v < 8; v++)
                mx = fmaxf(mx, fmaxf(s[v][2*h], s[v][2*h+1]));
            mx = fmaxf(mx, __shfl_xor_sync(0xffffffffu, mx, 1));
            mx = fmaxf(mx, __shfl_xor_sync(0xffffffffu, mx, 2));
            float mnew = fmaxf(m_i[h], mx);
            alpha[h] = __expf(m_i[h] - mnew);
            m_i[h] = mnew;
            float cbias = mnew * LOG2E;
            #pragma unroll
            for (int v = 0; v < 8; v++) {
                uint32_t arg = h2u(fmaf(s[v][2*h],   LOG2E, -cbias),
                                   fmaf(s[v][2*h+1], LOG2E, -cbias));
                ph[v][h] = ex2_h2(arg);
            }
            uint32_t t0 = hadd2u(ph[0][h], ph[1][h]);
            uint32_t t1 = hadd2u(ph[2][h], ph[3][h]);
            uint32_t t2 = hadd2u(ph[4][h], ph[5][h]);
            uint32_t t3 = hadd2u(ph[6][h], ph[7][h]);
            uint32_t q0 = hadd2u(t0, t1);
            uint32_t q1 = hadd2u(t2, t3);
            float2 f0 = u2f2(q0);
            float2 f1 = u2f2(q1);
            float rs = (f0.x + f0.y) + (f1.x + f1.y);
            l_p[h] = l_p[h] * alpha[h] + rs;
        }
        if (__any_sync(0xffffffffu, (alpha[0] != 1.0f) || (alpha[1] != 1.0f))) {
            #pragma unroll
            for (int v = 0; v < 8; v++) {
                o[v][0] *= alpha[0]; o[v][1] *= alpha[0];
                o[v][2] *= alpha[1]; o[v][3] *= alpha[1];
            }
        }

        // O_tile = P V in fp16-accumulator MMA; promote per tile to fp32 O
        #pragma unroll
        for (int w2 = 0; w2 < 4; w2++) {
            uint32_t d01[2] = {0u, 0u}, d23[2] = {0u, 0u};
            #pragma unroll
            for (int u = 0; u < 4; u++) {
                uint32_t pa[4] = {ph[2*u][0], ph[2*u][1],
                                  ph[2*u+1][0], ph[2*u+1][1]};
                int row = u*16 + (mat & 1) * 8 + (lane & 7);
                int colb = w2*32 + (mat >> 1) * 16;
                uint32_t off = (uint32_t)(row * 128 + colb);
                off ^= ((off >> 7) & 7) << 4;
                uint32_t r[4];
                ldm4t(r, vsb + off);
                mma_f16h(d01, pa, r[0], r[1]);
                mma_f16h(d23, pa, r[2], r[3]);
            }
            float2 a0 = u2f2(d01[0]), a1 = u2f2(d01[1]);
            float2 b0 = u2f2(d23[0]), b1 = u2f2(d23[1]);
            o[2*w2][0]   += a0.x; o[2*w2][1]   += a0.y;
            o[2*w2][2]   += a1.x; o[2*w2][3]   += a1.y;
            o[2*w2+1][0] += b0.x; o[2*w2+1][1] += b0.y;
            o[2*w2+1][2] += b1.x; o[2*w2+1][3] += b1.y;
        }
    }

    // epilogue: quad-reduce l, normalize + fp16 store
    #pragma unroll
    for (int h = 0; h < 2; h++) {
        float lsum = l_p[h];
        lsum += __shfl_xor_sync(0xffffffffu, lsum, 1);
        lsum += __shfl_xor_sync(0xffffffffu, lsum, 2);
        float inv = 1.f / lsum;
        int rowg = b * SEQ + n0 + wid*16 + h*8 + lr;
        #pragma unroll
        for (int v = 0; v < 8; v++) {
            int col = hd * 64 + v*8 + 2*lc;
            uint32_t pk = h2u(o[v][2*h] * inv, o[v][2*h+1] * inv);
            *reinterpret_cast<uint32_t*>(outh + (size_t)rowg * INNER + col) = pk;
        }
    }
}

// ---------------- launcher ---------------------------------------------------
extern "C" void kernel_launch(void* const* d_in, const int* in_sizes, int n_in,
                              void* d_out, int out_size)
{
    const float* x     = (const float*)d_in[0];
    const float* gamma = (const float*)d_in[1];
    const float* beta  = (const float*)d_in[2];
    const float* Wqkv  = (const float*)d_in[3];
    const float* Wout  = (const float*)d_in[4];
    const float* bout  = (const float*)d_in[5];
    float* out = (float*)d_out;

    __half *qkvh, *xnh, *wqh, *woh, *aoh;
    cudaGetSymbolAddress((void**)&qkvh, g_qkvh);
    cudaGetSymbolAddress((void**)&xnh, g_xnh);
    cudaGetSymbolAddress((void**)&wqh, g_wqh);
    cudaGetSymbolAddress((void**)&woh, g_woh);
    cudaGetSymbolAddress((void**)&aoh, g_aoh);

    cudaFuncSetAttribute(hf_gemm_kernel<true>,
                         cudaFuncAttributeMaxDynamicSharedMemorySize, HS_SMEM);
    cudaFuncSetAttribute(hf_gemm_kernel<false>,
                         cudaFuncAttributeMaxDynamicSharedMemorySize, HS_SMEM);
    cudaFuncSetAttribute(fa_kernel,
                         cudaFuncAttributeMaxDynamicSharedMemorySize, FAH_SMEM);

    ln_conv_kernel<<<ROWS + CONV_BLOCKS, 256>>>(
        x, gamma, beta, xnh, Wqkv, Wout, wqh, woh);

    hf_gemm_kernel<true><<<dim3(QKV3 / 128, ROWS / 128), 256, HS_SMEM>>>(
        xnh, wqh, nullptr, qkvh, QKV3);

    fa_kernel<<<dim3(SEQ / 128, HEADS, BATCH), 256, FAH_SMEM>>>(qkvh, aoh);

    hf_gemm_kernel<false><<<dim3(DIMSZ / 128, ROWS / 128), 256, HS_SMEM>>>(
        aoh, woh, bout, out, DIMSZ);
}

// round 17
// speedup vs baseline: 1.0639x; 1.0639x over previous
#include <cuda_runtime.h>
#include <cuda_bf16.h>
#include <cuda_fp16.h>
#include <cstdint>

#define BATCH 2
#define SEQ   2048
#define DIMSZ 1024
#define HEADS 16
#define DHEAD 64
#define INNER 1024
#define QKV3  3072
#define ROWS  (BATCH * SEQ)   // 4096

// ---------------- scratch (static device globals; no allocation) -------------
__device__ __half g_qkvh[ROWS * QKV3];    // 25 MB fp16 (Q prescaled by 0.125)
__device__ __half g_xnh[ROWS * DIMSZ];    // LN out fp16
__device__ __half g_wqh[DIMSZ * QKV3];    // Wqkv fp16, natural [K][N]
__device__ __half g_woh[INNER * DIMSZ];   // Wout fp16, natural [K][N]
__device__ __half g_aoh[ROWS * INNER];    // attention out fp16

// ---------------- helpers ----------------------------------------------------
__device__ __forceinline__ uint32_t smem_u32(const void* p) {
    uint32_t a;
    asm("{ .reg .u64 t; cvta.to.shared.u64 t, %1; cvt.u32.u64 %0, t; }"
        : "=r"(a) : "l"(p));
    return a;
}
__device__ __forceinline__ void cp16(uint32_t dst, const void* src) {
    asm volatile("cp.async.cg.shared.global [%0], [%1], 16;"
                 :: "r"(dst), "l"(src) : "memory");
}
__device__ __forceinline__ void ldm4(uint32_t* r, uint32_t addr) {
    asm volatile("ldmatrix.sync.aligned.m8n8.x4.shared.b16 {%0,%1,%2,%3}, [%4];"
        : "=r"(r[0]), "=r"(r[1]), "=r"(r[2]), "=r"(r[3]) : "r"(addr));
}
__device__ __forceinline__ void ldm4t(uint32_t* r, uint32_t addr) {
    asm volatile("ldmatrix.sync.aligned.m8n8.x4.trans.shared.b16 {%0,%1,%2,%3}, [%4];"
        : "=r"(r[0]), "=r"(r[1]), "=r"(r[2]), "=r"(r[3]) : "r"(addr));
}
__device__ __forceinline__ void mma_f16(float* d, const uint32_t* a,
                                        uint32_t b0, uint32_t b1) {
    asm volatile("mma.sync.aligned.m16n8k16.row.col.f32.f16.f16.f32 "
        "{%0,%1,%2,%3}, {%4,%5,%6,%7}, {%8,%9}, {%0,%1,%2,%3};"
        : "+f"(d[0]), "+f"(d[1]), "+f"(d[2]), "+f"(d[3])
        : "r"(a[0]), "r"(a[1]), "r"(a[2]), "r"(a[3]), "r"(b0), "r"(b1));
}
__device__ __forceinline__ uint32_t h2u(float a, float b) {
    __half2 h = __floats2half2_rn(a, b);
    return *reinterpret_cast<uint32_t*>(&h);
}
__device__ __forceinline__ float2 u2f2(uint32_t u) {
    return __half22float2(*reinterpret_cast<__half2*>(&u));
}
__device__ __forceinline__ uint32_t ex2_h2(uint32_t packed) {
    uint32_t r;
    asm("ex2.approx.f16x2 %0, %1;" : "=r"(r) : "r"(packed));
    return r;
}
__device__ __forceinline__ uint32_t hadd2u(uint32_t a, uint32_t b) {
    uint32_t r;
    asm("add.f16x2 %0, %1, %2;" : "=r"(r) : "r"(a), "r"(b));
    return r;
}

// ------------- fused LayerNorm (blocks < ROWS) + weight convert --------------
#define CONV_N1 ((QKV3 * DIMSZ) / 4)      // 786432 float4
#define CONV_N2 ((DIMSZ * INNER) / 4)     // 262144 float4
#define CONV_BLOCKS ((CONV_N1 + CONV_N2) / 256)   // 4096

__global__ void __launch_bounds__(256) ln_conv_kernel(
    const float* __restrict__ x, const float* __restrict__ gamma,
    const float* __restrict__ beta, __half* __restrict__ o,
    const float* __restrict__ w1, const float* __restrict__ w2,
    __half* __restrict__ o1, __half* __restrict__ o2)
{
    int t = threadIdx.x;
    if (blockIdx.x >= ROWS) {
        int idx = (blockIdx.x - ROWS) * 256 + t;
        if (idx < CONV_N1) {
            float4 v = reinterpret_cast<const float4*>(w1)[idx];
            uint2 pk = {h2u(v.x, v.y), h2u(v.z, v.w)};
            reinterpret_cast<uint2*>(o1)[idx] = pk;
        } else {
            float4 v = reinterpret_cast<const float4*>(w2)[idx - CONV_N1];
            uint2 pk = {h2u(v.x, v.y), h2u(v.z, v.w)};
            reinterpret_cast<uint2*>(o2)[idx - CONV_N1] = pk;
        }
        return;
    }
    int row = blockIdx.x;
    const float4* xr = reinterpret_cast<const float4*>(x + (size_t)row * DIMSZ);
    float4 v = xr[t];
    float s  = v.x + v.y + v.z + v.w;
    float ss = v.x*v.x + v.y*v.y + v.z*v.z + v.w*v.w;
    #pragma unroll
    for (int off = 16; off; off >>= 1) {
        s  += __shfl_xor_sync(0xffffffffu, s,  off);
        ss += __shfl_xor_sync(0xffffffffu, ss, off);
    }
    __shared__ float sbuf[8], ssbuf[8];
    __shared__ float s_mu, s_rstd;
    int w = t >> 5, lane = t & 31;
    if (lane == 0) { sbuf[w] = s; ssbuf[w] = ss; }
    __syncthreads();
    if (t == 0) {
        float S = 0.f, SS = 0.f;
        #pragma unroll
        for (int i = 0; i < 8; i++) { S += sbuf[i]; SS += ssbuf[i]; }
        float mu = S * (1.0f / DIMSZ);
        float var = SS * (1.0f / DIMSZ) - mu * mu;
        s_mu = mu; s_rstd = rsqrtf(var + 1e-5f);
    }
    __syncthreads();
    float mu = s_mu, rstd = s_rstd;
    float4 g  = reinterpret_cast<const float4*>(gamma)[t];
    float4 bt = reinterpret_cast<const float4*>(beta)[t];
    float o0 = (v.x - mu) * rstd * g.x + bt.x;
    float o1v = (v.y - mu) * rstd * g.y + bt.y;
    float o2v = (v.z - mu) * rstd * g.z + bt.z;
    float o3 = (v.w - mu) * rstd * g.w + bt.w;
    uint2 pk = {h2u(o0, o1v), h2u(o2v, o3)};
    *reinterpret_cast<uint2*>(o + (size_t)row * DIMSZ + t * 4) = pk;
}

// ---------------- fp16 warp-mma GEMM, BK=64, natural-layout B ----------------
#define HS_AROW   144
#define HS_AARR   (128 * HS_AROW)      // 18432
#define HS_BARR   (64 * 256)           // 16384
#define HS_STAGE  (HS_AARR + HS_BARR)  // 34816
#define HS_NSTAGE 3
#define HS_SMEM   (HS_NSTAGE * HS_STAGE)   // 104448

template <bool HALF_OUT>
__global__ void __launch_bounds__(256, 2) hf_gemm_kernel(
    const __half* __restrict__ A, const __half* __restrict__ B,
    const float* __restrict__ bias, void* __restrict__ Cv, int Ntot)
{
    extern __shared__ char sm[];
    const int tid = threadIdx.x, lane = tid & 31, wid = tid >> 5;
    const int wm = wid >> 2, wn = wid & 3;
    const int c0 = blockIdx.x * 128, r0 = blockIdx.y * 128;
    const int lr = lane >> 2, lc = lane & 3;
    uint32_t sbase = smem_u32(sm);

    auto issue = [&](int c, int st) {
        int k0 = c * 64;
        uint32_t sb = sbase + st * HS_STAGE;
        #pragma unroll
        for (int i = 0; i < 8; i++) {
            int q = tid + i * 256;
            if (q < 1024) {
                int row = q >> 3, seg = q & 7;
                cp16(sb + row * HS_AROW + seg * 16,
                     A + (size_t)(r0 + row) * 1024 + k0 + seg * 8);
            } else {
                int rem = q - 1024;
                int row = rem >> 4, seg = rem & 15;
                uint32_t off = (uint32_t)(row * 256 + seg * 16);
                off ^= (uint32_t)(row & 7) << 4;
                cp16(sb + HS_AARR + off,
                     B + (size_t)(k0 + row) * Ntot + c0 + seg * 8);
            }
        }
        asm volatile("cp.async.commit_group;" ::: "memory");
    };

    float acc[4][4][4];
    #pragma unroll
    for (int a = 0; a < 4; a++)
        #pragma unroll
        for (int b = 0; b < 4; b++)
            #pragma unroll
            for (int cc = 0; cc < 4; cc++) acc[a][b][cc] = 0.f;

    issue(0, 0);
    issue(1, 1);

    const int mat  = lane >> 3;
    const int roff = (mat & 1) * 8 + (lane & 7);
    const int cofs = (mat >> 1) * 16;
    const uint32_t swzB = (uint32_t)(lane & 7) << 4;

    const int NCHUNK = 1024 / 64;   // 16
    int st = 0;
    for (int c = 0; c < NCHUNK; c++) {
        asm volatile("cp.async.wait_group 1;" ::: "memory");
        __syncthreads();

        int st2 = st + 2; if (st2 >= 3) st2 -= 3;
        if (c + 2 < NCHUNK) issue(c + 2, st2);
        else asm volatile("cp.async.commit_group;" ::: "memory");

        uint32_t base = sbase + st * HS_STAGE;

        #pragma unroll
        for (int ks = 0; ks < 4; ks++) {
            uint32_t ah[4][4], bh[2][4];
            #pragma unroll
            for (int nt2 = 0; nt2 < 2; nt2++) {
                uint32_t off = (uint32_t)((ks*16 + roff) * 256
                                          + wn*64 + nt2*32 + cofs) ^ swzB;
                ldm4t(bh[nt2], base + HS_AARR + off);
            }
            #pragma unroll
            for (int mt = 0; mt < 4; mt++)
                ldm4(ah[mt], base + (wm*64 + mt*16 + roff) * HS_AROW
                              + ks*32 + cofs);

            #pragma unroll
            for (int mt = 0; mt < 4; mt++)
                #pragma unroll
                for (int nt = 0; nt < 4; nt++) {
                    int n2 = nt >> 1, hf = nt & 1;
                    mma_f16(acc[mt][nt], ah[mt], bh[n2][2*hf], bh[n2][2*hf+1]);
                }
        }
        if (++st >= 3) st = 0;
    }

    #pragma unroll
    for (int mt = 0; mt < 4; mt++) {
        int rbase = r0 + wm*64 + mt*16 + lr;
        #pragma unroll
        for (int nt = 0; nt < 4; nt++) {
            int col = c0 + wn*32 + nt*8 + 2*lc;
            if (HALF_OUT) {
                __half* C = (__half*)Cv;
                float sc = (col < 1024) ? 0.125f : 1.0f;   // Q prescale
                *reinterpret_cast<uint32_t*>(C + (size_t)rbase * Ntot + col) =
                    h2u(acc[mt][nt][0] * sc, acc[mt][nt][1] * sc);
                *reinterpret_cast<uint32_t*>(C + (size_t)(rbase + 8) * Ntot + col) =
                    h2u(acc[mt][nt][2] * sc, acc[mt][nt][3] * sc);
            } else {
                float* C = (float*)Cv;
                float b0v = bias ? bias[col] : 0.f;
                float b1v = bias ? bias[col + 1] : 0.f;
                float2 v0 = {acc[mt][nt][0] + b0v, acc[mt][nt][1] + b1v};
                float2 v1 = {acc[mt][nt][2] + b0v, acc[mt][nt][3] + b1v};
                *reinterpret_cast<float2*>(C + (size_t)rbase * Ntot + col) = v0;
                *reinterpret_cast<float2*>(C + (size_t)(rbase + 8) * Ntot + col) = v1;
            }
        }
    }
}

// ---------------- flash attention: fp16 QK + f16x2 softmax -------------------
// Pointers pre-offset per batch; grid = (SEQ/128, HEADS, 1).
#define FA_QS    18432                    // Q: 128 * 144
#define FA_KB    9216                     // K stage: 64 * 144
#define FA_VB    8192                     // V stage: 64 * 128
#define FA_STAGE (FA_KB + FA_VB)          // 17408
#define FAH_SMEM (FA_QS + 2 * FA_STAGE)   // 53248

__global__ void __launch_bounds__(256, 2) fa_kernel(
    const __half* __restrict__ qkvb, __half* __restrict__ outb)
{
    extern __shared__ char sm[];
    const int tid = threadIdx.x, lane = tid & 31, wid = tid >> 5;
    const int qt = blockIdx.x, hd = blockIdx.y;
    const int n0 = qt * 128;
    const int lr = lane >> 2, lc = lane & 3;
    uint32_t sbase = smem_u32(sm);

    const __half* qb = qkvb + hd * DHEAD;
    const __half* kb = qb + 1024;
    const __half* vb = qb + 2048;

    #pragma unroll
    for (int i = 0; i < 4; i++) {
        int q = tid + i * 256;
        int row = q >> 3, ch = q & 7;
        cp16(sbase + row * 144 + ch * 16,
             qb + (size_t)(n0 + row) * QKV3 + ch * 8);
    }
    asm volatile("cp.async.commit_group;" ::: "memory");

    auto issueKV = [&](int kt, int st) {
        int s0 = kt * 64;
        uint32_t kbase = sbase + FA_QS + st * FA_STAGE;
        uint32_t vbase = kbase + FA_KB;
        #pragma unroll
        for (int i = 0; i < 4; i++) {
            int q = tid + i * 256;
            int arr = q >> 9, rem = q & 511;
            int row = rem >> 3, ch = rem & 7;
            if (arr == 0) {
                cp16(kbase + row * 144 + ch * 16,
                     kb + (size_t)(s0 + row) * QKV3 + ch * 8);
            } else {
                uint32_t off = (uint32_t)(row * 128 + ch * 16);
                off ^= ((off >> 7) & 7) << 4;
                cp16(vbase + off, vb + (size_t)(s0 + row) * QKV3 + ch * 8);
            }
        }
        asm volatile("cp.async.commit_group;" ::: "memory");
    };

    issueKV(0, 0);
    asm volatile("cp.async.wait_group 0;" ::: "memory");
    __syncthreads();

    const uint32_t* Qs = reinterpret_cast<const uint32_t*>(sm);
    uint32_t qa[4][4];
    {
        int m0 = wid * 16;
        #pragma unroll
        for (int u = 0; u < 4; u++) {
            qa[u][0] = Qs[(m0 + lr)     * 36 + u*8 + lc];
            qa[u][1] = Qs[(m0 + 8 + lr) * 36 + u*8 + lc];
            qa[u][2] = Qs[(m0 + lr)     * 36 + u*8 + lc + 4];
            qa[u][3] = Qs[(m0 + 8 + lr) * 36 + u*8 + lc + 4];
        }
    }

    const int mat  = lane >> 3;
    const int roff = (mat & 1) * 8 + (lane & 7);
    const int cofs = (mat >> 1) * 16;
    const float LOG2E = 1.44269504f;

    float m_i[2] = {-1e30f, -1e30f};
    float l_p[2] = {0.f, 0.f};
    float o[8][4];
    #pragma unroll
    for (int v = 0; v < 8; v++)
        #pragma unroll
        for (int j = 0; j < 4; j++) o[v][j] = 0.f;

    const int NT = SEQ / 64;   // 32
    for (int kt = 0; kt < NT; kt++) {
        if (kt > 0) {
            asm volatile("cp.async.wait_group 0;" ::: "memory");
            __syncthreads();
        }
        if (kt + 1 < NT) issueKV(kt + 1, (kt + 1) & 1);

        int st = kt & 1;
        uint32_t kbase = sbase + FA_QS + st * FA_STAGE;
        const uint32_t vsb = kbase + FA_KB;

        float s[8][4];
        #pragma unroll
        for (int v = 0; v < 8; v++)
            #pragma unroll
            for (int j = 0; j < 4; j++) s[v][j] = 0.f;
        #pragma unroll
        for (int u = 0; u < 4; u++) {
            uint32_t bh[4][4];
            #pragma unroll
            for (int g = 0; g < 4; g++)
                ldm4(bh[g], kbase + (g*16 + roff) * 144 + u*32 + cofs);
            #pragma unroll
            for (int v = 0; v < 8; v++) {
                int g = v >> 1, hf = v & 1;
                mma_f16(s[v], qa[u], bh[g][hf], bh[g][2+hf]);
            }
        }

        // online softmax; deferred l reduction, half2 sum tree
        uint32_t ph[8][2];
        float alpha[2];
        #pragma unroll
        for (int h = 0; h < 2; h++) {
            float mx = -1e30f;
            #pragma unroll
            for (int v = 0; v < 8; v++)
                mx = fmaxf(mx, fmaxf(s[v][2*h], s[v][2*h+1]));
            mx = fmaxf(mx, __shfl_xor_sync(0xffffffffu, mx, 1));
            mx = fmaxf(mx, __shfl_xor_sync(0xffffffffu, mx, 2));
            float mnew = fmaxf(m_i[h], mx);
            alpha[h] = __expf(m_i[h] - mnew);
            m_i[h] = mnew;
            float cbias = mnew * LOG2E;
            #pragma unroll
            for (int v = 0; v < 8; v++) {
                uint32_t arg = h2u(fmaf(s[v][2*h],   LOG2E, -cbias),
                                   fmaf(s[v][2*h+1], LOG2E, -cbias));
                ph[v][h] = ex2_h2(arg);
            }
            uint32_t t0 = hadd2u(ph[0][h], ph[1][h]);
            uint32_t t1 = hadd2u(ph[2][h], ph[3][h]);
            uint32_t t2 = hadd2u(ph[4][h], ph[5][h]);
            uint32_t t3 = hadd2u(ph[6][h], ph[7][h]);
            uint32_t q0 = hadd2u(t0, t1);
            uint32_t q1 = hadd2u(t2, t3);
            float2 f0 = u2f2(q0);
            float2 f1 = u2f2(q1);
            float rs = (f0.x + f0.y) + (f1.x + f1.y);
            l_p[h] = l_p[h] * alpha[h] + rs;
        }
        if (__any_sync(0xffffffffu, (alpha[0] != 1.0f) || (alpha[1] != 1.0f))) {
            #pragma unroll
            for (int v = 0; v < 8; v++) {
                o[v][0] *= alpha[0]; o[v][1] *= alpha[0];
                o[v][2] *= alpha[1]; o[v][3] *= alpha[1];
            }
        }

        #pragma unroll
        for (int u = 0; u < 4; u++) {
            uint32_t pa[4] = {ph[2*u][0], ph[2*u][1], ph[2*u+1][0], ph[2*u+1][1]};
            #pragma unroll
            for (int w2 = 0; w2 < 4; w2++) {
                int row = u*16 + (mat & 1) * 8 + (lane & 7);
                int colb = w2*32 + (mat >> 1) * 16;
                uint32_t off = (uint32_t)(row * 128 + colb);
                off ^= ((off >> 7) & 7) << 4;
                uint32_t r[4];
                ldm4t(r, vsb + off);
                mma_f16(o[2*w2],     pa, r[0], r[1]);
                mma_f16(o[2*w2 + 1], pa, r[2], r[3]);
            }
        }
    }

    // epilogue: quad-reduce l, normalize + fp16 store
    #pragma unroll
    for (int h = 0; h < 2; h++) {
        float lsum = l_p[h];
        lsum += __shfl_xor_sync(0xffffffffu, lsum, 1);
        lsum += __shfl_xor_sync(0xffffffffu, lsum, 2);
        float inv = 1.f / lsum;
        int rowg = n0 + wid*16 + h*8 + lr;
        #pragma unroll
        for (int v = 0; v < 8; v++) {
            int col = hd * 64 + v*8 + 2*lc;
            uint32_t pk = h2u(o[v][2*h] * inv, o[v][2*h+1] * inv);
            *reinterpret_cast<uint32_t*>(outb + (size_t)rowg * INNER + col) = pk;
        }
    }
}

// ---------------- launcher: split-batch cross-stream pipeline ----------------
extern "C" void kernel_launch(void* const* d_in, const int* in_sizes, int n_in,
                              void* d_out, int out_size)
{
    const float* x     = (const float*)d_in[0];
    const float* gamma = (const float*)d_in[1];
    const float* beta  = (const float*)d_in[2];
    const float* Wqkv  = (const float*)d_in[3];
    const float* Wout  = (const float*)d_in[4];
    const float* bout  = (const float*)d_in[5];
    float* out = (float*)d_out;

    __half *qkvh, *xnh, *wqh, *woh, *aoh;
    cudaGetSymbolAddress((void**)&qkvh, g_qkvh);
    cudaGetSymbolAddress((void**)&xnh, g_xnh);
    cudaGetSymbolAddress((void**)&wqh, g_wqh);
    cudaGetSymbolAddress((void**)&woh, g_woh);
    cudaGetSymbolAddress((void**)&aoh, g_aoh);

    cudaFuncSetAttribute(hf_gemm_kernel<true>,
                         cudaFuncAttributeMaxDynamicSharedMemorySize, HS_SMEM);
    cudaFuncSetAttribute(hf_gemm_kernel<false>,
                         cudaFuncAttributeMaxDynamicSharedMemorySize, HS_SMEM);
    cudaFuncSetAttribute(fa_kernel,
                         cudaFuncAttributeMaxDynamicSharedMemorySize, FAH_SMEM);

    cudaStream_t s2;
    cudaStreamCreateWithFlags(&s2, cudaStreamNonBlocking);
    cudaEvent_t e0, e2;
    cudaEventCreateWithFlags(&e0, cudaEventDisableTiming);
    cudaEventCreateWithFlags(&e2, cudaEventDisableTiming);

    // s0: LN + weight convert
    ln_conv_kernel<<<ROWS + CONV_BLOCKS, 256>>>(
        x, gamma, beta, xnh, Wqkv, Wout, wqh, woh);

    // s0: QKV GEMM, batch-0 rows
    hf_gemm_kernel<true><<<dim3(QKV3 / 128, SEQ / 128), 256, HS_SMEM>>>(
        xnh, wqh, nullptr, qkvh, QKV3);
    cudaEventRecord(e0, 0);

    // s0: QKV GEMM, batch-1 rows
    hf_gemm_kernel<true><<<dim3(QKV3 / 128, SEQ / 128), 256, HS_SMEM>>>(
        xnh + (size_t)SEQ * DIMSZ, wqh, nullptr,
        qkvh + (size_t)SEQ * QKV3, QKV3);

    // s2: flash batch 0 (overlaps with QKV b1 + flash b1 ramp)
    cudaStreamWaitEvent(s2, e0, 0);
    fa_kernel<<<dim3(SEQ / 128, HEADS, 1), 256, FAH_SMEM, s2>>>(
        qkvh, aoh);
    cudaEventRecord(e2, s2);

    // s0: flash batch 1
    fa_kernel<<<dim3(SEQ / 128, HEADS, 1), 256, FAH_SMEM>>>(
        qkvh + (size_t)SEQ * QKV3, aoh + (size_t)SEQ * INNER);

    // s0 joins s2, then out-projection
    cudaStreamWaitEvent(0, e2, 0);
    hf_gemm_kernel<false><<<dim3(DIMSZ / 128, ROWS / 128), 256, HS_SMEM>>>(
        aoh, woh, bout, out, DIMSZ);

    cudaEventDestroy(e0);
    cudaEventDestroy(e2);
    cudaStreamDestroy(s2);
}